// round 4
// baseline (speedup 1.0000x reference)
#include <cuda_runtime.h>
#include <cuda_bf16.h>

#define B 4
#define C 128
#define CM 64
#define CO 100
#define HO 128
#define WO 128

typedef unsigned long long u64;

__device__ __forceinline__ u64 pk(float lo, float hi) {
    u64 r; asm("mov.b64 %0, {%1,%2};" : "=l"(r) : "f"(lo), "f"(hi)); return r;
}
__device__ __forceinline__ float2 upk(u64 v) {
    float2 f; asm("mov.b64 {%0,%1}, %2;" : "=f"(f.x), "=f"(f.y) : "l"(v)); return f;
}
__device__ __forceinline__ u64 swp(u64 v) {           // swap 32-bit halves
    float2 f = upk(v); return pk(f.y, f.x);
}
#define FMA2(d,a,b) asm("fma.rn.f32x2 %0, %1, %2, %0;" : "+l"(d) : "l"(a), "l"(b))
#define MUL2(d,a,b) asm("mul.rn.f32x2 %0, %1, %2;" : "=l"(d) : "l"(a), "l"(b))

// scratch
__device__ float g_wc[C*CM];          // comp weights [c][m], BN-scaled
__device__ float g_we[CM*9*CO];       // enc weights  [c][tap][o], BN-scaled
__device__ float g_W1[B*CM*64*64];    // conv1x1+SiLU activations
__device__ float g_W2[B*CO*64*64];    // conv3x3+BN logits

// ---------------------------------------------------------------------------
// K0: fold BN scale into weights and transpose
// ---------------------------------------------------------------------------
__global__ void k0_prep(const float* __restrict__ cw, const float* __restrict__ cg,
                        const float* __restrict__ ew, const float* __restrict__ eg) {
    int i = blockIdx.x * blockDim.x + threadIdx.x;
    const float s = rsqrtf(1.0f + 1e-5f);
    if (i < C*CM) {
        int c = i >> 6, m = i & 63;
        g_wc[i] = cw[m*C + c] * (cg[m] * s);
    }
    if (i < CM*9*CO) {
        int c = i / 900, r = i - c*900, t = r / 100, o = r - t*100;
        g_we[i] = ew[(o*CM + c)*9 + t] * (eg[o] * s);
    }
}

// ---------------------------------------------------------------------------
// K1: 1x1 conv (128->64) + BN bias + SiLU.  Tile 64m x 64px, grid 256.
// m-pair accumulators: weights natural u64 pairs; x duplicated in smem.
// Inner c-step: 3 LDS.128 + 8 FFMA2, zero MOVs.
// ---------------------------------------------------------------------------
__global__ __launch_bounds__(256) void k1_comp(const float* __restrict__ X,
                                               const float* __restrict__ cb) {
    __shared__ __align__(16) float ws[16*64];
    __shared__ __align__(16) u64  xsd[16*64];    // duplicated (v,v)
    int blk = blockIdx.x;
    int b   = blk >> 6;
    int hw0 = (blk & 63) * 64;
    int tid = threadIdx.x, mg = tid >> 4, pxl = (tid & 15) * 4;

    u64 a01[4], a23[4];
#pragma unroll
    for (int p = 0; p < 4; p++) { a01[p] = 0ull; a23[p] = 0ull; }

    for (int c0 = 0; c0 < C; c0 += 16) {
        __syncthreads();
        {
            int c = tid >> 4, px = (tid & 15) * 4;
            float4 v = *(const float4*)&X[(b*C + c0 + c)*4096 + hw0 + px];
            *(float4*)&xsd[c*64 + px]     = make_float4(v.x, v.x, v.y, v.y);
            *(float4*)&xsd[c*64 + px + 2] = make_float4(v.z, v.z, v.w, v.w);
            *(float4*)&ws[tid*4] = *(const float4*)&g_wc[c0*64 + tid*4];
        }
        __syncthreads();
#pragma unroll
        for (int c = 0; c < 16; c++) {
            ulonglong2 wp = *(const ulonglong2*)&ws[c*64 + mg*4];
            ulonglong2 xA = *(const ulonglong2*)&xsd[c*64 + pxl];
            ulonglong2 xB = *(const ulonglong2*)&xsd[c*64 + pxl + 2];
            u64 xx[4] = {xA.x, xA.y, xB.x, xB.y};
#pragma unroll
            for (int p = 0; p < 4; p++) {
                FMA2(a01[p], wp.x, xx[p]);
                FMA2(a23[p], wp.y, xx[p]);
            }
        }
    }
    float4 bias = *(const float4*)&cb[mg*4];
    float o0[4], o1[4], o2[4], o3[4];
#pragma unroll
    for (int p = 0; p < 4; p++) {
        float2 f01 = upk(a01[p]), f23 = upk(a23[p]);
        o0[p] = f01.x + bias.x; o1[p] = f01.y + bias.y;
        o2[p] = f23.x + bias.z; o3[p] = f23.y + bias.w;
    }
#define SILU4(v) { v[0] /= 1.f+__expf(-v[0]); v[1] /= 1.f+__expf(-v[1]); \
                   v[2] /= 1.f+__expf(-v[2]); v[3] /= 1.f+__expf(-v[3]); }
    SILU4(o0); SILU4(o1); SILU4(o2); SILU4(o3);
    float* dst = &g_W1[(b*CM + mg*4)*4096 + hw0 + pxl];
    *(float4*)(dst)         = make_float4(o0[0],o0[1],o0[2],o0[3]);
    *(float4*)(dst + 4096)  = make_float4(o1[0],o1[1],o1[2],o1[3]);
    *(float4*)(dst + 8192)  = make_float4(o2[0],o2[1],o2[2],o2[3]);
    *(float4*)(dst + 12288) = make_float4(o3[0],o3[1],o3[2],o3[3]);
}

// ---------------------------------------------------------------------------
// K2: 3x3 conv (64->100) + BN bias.  Tile 100o x (4x8)px, grid 512.
// o-pair accumulators: weights LDS.128 -> two u64 pairs; x duplicated in smem,
// 3 LDS.128 per (c,row).  Per tap: 1 LDS.128 + 8 FFMA2, zero MOVs.
// ---------------------------------------------------------------------------
__global__ __launch_bounds__(200, 4) void k2_enc(const float* __restrict__ eb) {
    __shared__ __align__(16) u64  xsd[8*6*10];   // [c][6 rows][10 cols] dup
    __shared__ __align__(16) float ws[8*900];    // [c][9 taps][100 o]
    int blk  = blockIdx.x;
    int b    = blk >> 7;
    int tile = blk & 127;
    int y0   = (tile >> 3)*4, x0 = (tile & 7)*8;
    int tid  = threadIdx.x;
    int og   = tid >> 3, pg = tid & 7;
    int prow = pg >> 1, pcol = (pg & 1)*4;

    u64 a01[4], a23[4];
#pragma unroll
    for (int p = 0; p < 4; p++) { a01[p] = 0ull; a23[p] = 0ull; }

    for (int c0 = 0; c0 < CM; c0 += 8) {
        __syncthreads();
        for (int k = tid; k < 480; k += 200) {
            int c = k / 60, p = k - c*60, r = p / 10, cl = p - r*10;
            int y = y0 + r - 1, x = x0 + cl - 1;
            float v = 0.f;
            if ((unsigned)y < 64u && (unsigned)x < 64u)
                v = g_W1[(b*CM + c0 + c)*4096 + y*64 + x];
            *(float2*)&xsd[c*60 + r*10 + cl] = make_float2(v, v);
        }
        {
            const float4* src = (const float4*)&g_we[c0*900];
            float4* dst = (float4*)ws;
#pragma unroll
            for (int j = 0; j < 9; j++) dst[tid + j*200] = src[tid + j*200];
        }
        __syncthreads();

#pragma unroll
        for (int c = 0; c < 8; c++) {
#pragma unroll
            for (int ti = 0; ti < 3; ti++) {
                const u64* rb = &xsd[c*60 + (prow + ti)*10 + pcol];
                ulonglong2 xA = *(const ulonglong2*)rb;
                ulonglong2 xB = *(const ulonglong2*)(rb + 2);
                ulonglong2 xC = *(const ulonglong2*)(rb + 4);
                u64 xx[6] = {xA.x, xA.y, xB.x, xB.y, xC.x, xC.y};
#pragma unroll
                for (int tj = 0; tj < 3; tj++) {
                    ulonglong2 wp = *(const ulonglong2*)&ws[c*900 + (ti*3 + tj)*100 + og*4];
#pragma unroll
                    for (int p = 0; p < 4; p++) {
                        FMA2(a01[p], wp.x, xx[tj + p]);
                        FMA2(a23[p], wp.y, xx[tj + p]);
                    }
                }
            }
        }
    }
    float4 bias = *(const float4*)&eb[og*4];
    int rowbase = (y0 + prow)*64 + x0 + pcol;
    float* d0 = &g_W2[(b*CO + og*4)*4096 + rowbase];
    float o0[4], o1[4], o2[4], o3[4];
#pragma unroll
    for (int p = 0; p < 4; p++) {
        float2 f01 = upk(a01[p]), f23 = upk(a23[p]);
        o0[p] = f01.x + bias.x; o1[p] = f01.y + bias.y;
        o2[p] = f23.x + bias.z; o3[p] = f23.y + bias.w;
    }
    *(float4*)(d0)          = make_float4(o0[0],o0[1],o0[2],o0[3]);
    *(float4*)(d0 + 4096)   = make_float4(o1[0],o1[1],o1[2],o1[3]);
    *(float4*)(d0 + 8192)   = make_float4(o2[0],o2[1],o2[2],o2[3]);
    *(float4*)(d0 + 12288)  = make_float4(o3[0],o3[1],o3[2],o3[3]);
}

// ---------------------------------------------------------------------------
// K3: pixel-shuffle + softmax(25) + CARAFE combine, fused.
// Channel-PAIR packing: smem holds interleaved (X[c],X[c+1]) u64 pairs.
// Per tap per c-pair: 1 LDS.64 + 1 swap(2 MOV) + 4 FFMA2 -> 8 lane-FMAs.
// ---------------------------------------------------------------------------
__global__ __launch_bounds__(128, 4) void k3_carafe(const float* __restrict__ X,
                                                    float* __restrict__ out) {
    __shared__ __align__(16) u64 xs2[2*240];   // [2 pairs][12 rows][20 cols]
    int blk    = blockIdx.x;
    int cq     = blk >> 7;          // channel quarter (32 ch)
    int tileid = blk & 127;
    int b  = tileid >> 5;
    int t  = tileid & 31;
    int ty = t >> 2, tx = t & 3;
    int tid = threadIdx.x;
    int py  = tid >> 4, pxl = tid & 15;
    int y0g = ty*8 + py, x0g = tx*16 + pxl;

    // softmax over 25 taps for 4 subpixels; packed (s0,s1),(s2,s3)
    u64 w01[25], w23[25];
    {
        const float* base = g_W2 + (size_t)b*CO*4096 + y0g*64 + x0g;
        float s0 = 0.f, s1 = 0.f, s2 = 0.f, s3 = 0.f;
#pragma unroll
        for (int k = 0; k < 25; k++) {
            float e0 = __expf(base[(k*4 + 0)*4096]); s0 += e0;
            float e1 = __expf(base[(k*4 + 1)*4096]); s1 += e1;
            w01[k] = pk(e0, e1);
            float e2 = __expf(base[(k*4 + 2)*4096]); s2 += e2;
            float e3 = __expf(base[(k*4 + 3)*4096]); s3 += e3;
            w23[k] = pk(e2, e3);
        }
        u64 i01 = pk(1.0f/s0, 1.0f/s1);
        u64 i23 = pk(1.0f/s2, 1.0f/s3);
#pragma unroll
        for (int k = 0; k < 25; k++) {
            MUL2(w01[k], w01[k], i01);
            MUL2(w23[k], w23[k], i23);
        }
    }

    int cbase = cq*32;
    int ybase = ty*8 - 2, xbase = tx*16 - 2;
    for (int c0 = 0; c0 < 32; c0 += 4) {          // 2 channel-pairs per round
        __syncthreads();
        for (int k = tid; k < 480; k += 128) {
            int pr = k / 240, p = k - pr*240, r = p / 20, cl = p - r*20;
            int y = ybase + r, x = xbase + cl;
            float va = 0.f, vb = 0.f;
            if ((unsigned)y < 64u && (unsigned)x < 64u) {
                const float* xp = &X[((b*C + cbase + c0 + pr*2)*64 + y)*64 + x];
                va = xp[0];
                vb = xp[4096];
            }
            *(float2*)&xs2[pr*240 + r*20 + cl] = make_float2(va, vb);
        }
        __syncthreads();
#pragma unroll
        for (int pr = 0; pr < 2; pr++) {
            u64 aA = 0ull, aB = 0ull, aC = 0ull, aD = 0ull;
            const u64* xp = &xs2[pr*240 + py*20 + pxl];
#pragma unroll
            for (int i = 0; i < 5; i++)
#pragma unroll
                for (int j = 0; j < 5; j++) {
                    u64 xcc = xp[i*20 + j];
                    u64 xss = swp(xcc);
                    int kk = i*5 + j;
                    FMA2(aA, w01[kk], xcc);
                    FMA2(aB, w01[kk], xss);
                    FMA2(aC, w23[kk], xcc);
                    FMA2(aD, w23[kk], xss);
                }
            // ca: s0=aA.x s1=aB.y s2=aC.x s3=aD.y ; cb: s0=aB.x s1=aA.y s2=aD.x s3=aC.y
            float2 fA = upk(aA), fB = upk(aB), fC = upk(aC), fD = upk(aD);
            int ca = cbase + c0 + pr*2;
            size_t ob = ((size_t)(b*C + ca)*HO + 2*y0g)*WO + 2*x0g;
            *(float2*)&out[ob]              = make_float2(fA.x, fB.y);
            *(float2*)&out[ob + WO]         = make_float2(fC.x, fD.y);
            *(float2*)&out[ob + (size_t)HO*WO]      = make_float2(fB.x, fA.y);
            *(float2*)&out[ob + (size_t)HO*WO + WO] = make_float2(fD.x, fC.y);
        }
    }
}

// ---------------------------------------------------------------------------
extern "C" void kernel_launch(void* const* d_in, const int* in_sizes, int n_in,
                              void* d_out, int out_size) {
    const float* X      = (const float*)d_in[0];
    const float* comp_w = (const float*)d_in[1];
    const float* comp_g = (const float*)d_in[2];
    const float* comp_b = (const float*)d_in[3];
    const float* enc_w  = (const float*)d_in[4];
    const float* enc_g  = (const float*)d_in[5];
    const float* enc_b  = (const float*)d_in[6];
    float* out = (float*)d_out;

    k0_prep  <<<225, 256>>>(comp_w, comp_g, enc_w, enc_g);
    k1_comp  <<<256, 256>>>(X, comp_b);
    k2_enc   <<<512, 200>>>(enc_b);
    k3_carafe<<<512, 128>>>(X, out);
}